// round 2
// baseline (speedup 1.0000x reference)
#include <cuda_runtime.h>

#define H 128
#define MAX_ROWS 100000
#define TILE_ROWS 64

// Scratch tables: A = user @ W1_top + b1,  B = movie @ W1_bot
__device__ float g_A[(size_t)MAX_ROWS * H];
__device__ float g_B[(size_t)MAX_ROWS * H];

// ---------------------------------------------------------------------------
// Precompute: out[n_rows, 128] = X[n_rows, 128] @ W[128, 128] (+ bias)
// Block: 64 rows x 128 cols, 256 threads, each thread an 8x4 register tile.
// W (64KB) + X tile (32KB) in dynamic smem.
// ---------------------------------------------------------------------------
__global__ __launch_bounds__(256, 2)
void precompute_kernel(const float* __restrict__ X,
                       const float* __restrict__ W,
                       const float* __restrict__ bias,
                       float* __restrict__ out,
                       int n_rows)
{
    extern __shared__ float smem[];
    float* Ws = smem;              // [128][128]
    float* Xs = smem + H * H;      // [64][128]

    const int tid = threadIdx.x;

    // Load W fully: 16384 floats = 4096 float4, 16 per thread
    {
        const float4* Wv = (const float4*)W;
        float4* Wsv = (float4*)Ws;
        #pragma unroll
        for (int i = 0; i < 16; i++)
            Wsv[tid + i * 256] = Wv[tid + i * 256];
    }

    const int row0 = blockIdx.x * TILE_ROWS;

    // Load X tile: 64 rows x 32 float4 = 2048 float4, 8 per thread
    {
        const float4* Xv = (const float4*)X;
        float4* Xsv = (float4*)Xs;
        #pragma unroll
        for (int i = 0; i < 8; i++) {
            int idx = tid + i * 256;
            int r = idx >> 5;          // 32 float4 per row
            int c = idx & 31;
            float4 v = make_float4(0.f, 0.f, 0.f, 0.f);
            if (row0 + r < n_rows)
                v = Xv[(size_t)(row0 + r) * 32 + c];
            Xsv[idx] = v;
        }
    }
    __syncthreads();

    const int jlane = tid & 31;    // column group: cols jlane*4 .. jlane*4+3
    const int rgrp  = tid >> 5;    // row group: rows rgrp*8 .. rgrp*8+7

    float acc[8][4];
    #pragma unroll
    for (int r = 0; r < 8; r++) {
        acc[r][0] = 0.f; acc[r][1] = 0.f; acc[r][2] = 0.f; acc[r][3] = 0.f;
    }

    #pragma unroll 4
    for (int k = 0; k < H; k += 4) {
        float4 w0 = *(const float4*)&Ws[(k + 0) * H + jlane * 4];
        float4 w1 = *(const float4*)&Ws[(k + 1) * H + jlane * 4];
        float4 w2 = *(const float4*)&Ws[(k + 2) * H + jlane * 4];
        float4 w3 = *(const float4*)&Ws[(k + 3) * H + jlane * 4];
        #pragma unroll
        for (int r = 0; r < 8; r++) {
            float4 x = *(const float4*)&Xs[(rgrp * 8 + r) * H + k];
            acc[r][0] = fmaf(x.x, w0.x, acc[r][0]);
            acc[r][1] = fmaf(x.x, w0.y, acc[r][1]);
            acc[r][2] = fmaf(x.x, w0.z, acc[r][2]);
            acc[r][3] = fmaf(x.x, w0.w, acc[r][3]);
            acc[r][0] = fmaf(x.y, w1.x, acc[r][0]);
            acc[r][1] = fmaf(x.y, w1.y, acc[r][1]);
            acc[r][2] = fmaf(x.y, w1.z, acc[r][2]);
            acc[r][3] = fmaf(x.y, w1.w, acc[r][3]);
            acc[r][0] = fmaf(x.z, w2.x, acc[r][0]);
            acc[r][1] = fmaf(x.z, w2.y, acc[r][1]);
            acc[r][2] = fmaf(x.z, w2.z, acc[r][2]);
            acc[r][3] = fmaf(x.z, w2.w, acc[r][3]);
            acc[r][0] = fmaf(x.w, w3.x, acc[r][0]);
            acc[r][1] = fmaf(x.w, w3.y, acc[r][1]);
            acc[r][2] = fmaf(x.w, w3.z, acc[r][2]);
            acc[r][3] = fmaf(x.w, w3.w, acc[r][3]);
        }
    }

    float4 bv = make_float4(0.f, 0.f, 0.f, 0.f);
    if (bias) bv = *(const float4*)&bias[jlane * 4];

    #pragma unroll
    for (int r = 0; r < 8; r++) {
        int row = row0 + rgrp * 8 + r;
        if (row < n_rows) {
            float4 o;
            o.x = acc[r][0] + bv.x;
            o.y = acc[r][1] + bv.y;
            o.z = acc[r][2] + bv.z;
            o.w = acc[r][3] + bv.w;
            *(float4*)&out[(size_t)row * H + jlane * 4] = o;
        }
    }
}

// ---------------------------------------------------------------------------
// Edge phase: out[e] = relu(A[src[e]] + B[dst[e]]) . W2 + b2
// One warp per edge, 2-edge unroll for memory-level parallelism.
// ---------------------------------------------------------------------------
__global__ __launch_bounds__(256)
void edge_kernel(const int* __restrict__ ei,
                 const float* __restrict__ W2,
                 const float* __restrict__ b2,
                 float* __restrict__ out,
                 int E)
{
    const int lane = threadIdx.x & 31;
    const int gw   = (blockIdx.x * blockDim.x + threadIdx.x) >> 5;
    const int nw   = (gridDim.x * blockDim.x) >> 5;

    const float4 w2 = *(const float4*)&W2[lane * 4];
    const float  b2v = b2[0];

    for (int e0 = gw * 2; e0 < E; e0 += nw * 2) {
        const int e1   = e0 + 1;
        const bool has1 = (e1 < E);
        const int ee1  = has1 ? e1 : e0;

        int s0 = ei[e0], d0 = ei[E + e0];
        int s1 = ei[ee1], d1 = ei[E + ee1];

        float4 a0  = *(const float4*)&g_A[(size_t)s0 * H + lane * 4];
        float4 bb0 = *(const float4*)&g_B[(size_t)d0 * H + lane * 4];
        float4 a1  = *(const float4*)&g_A[(size_t)s1 * H + lane * 4];
        float4 bb1 = *(const float4*)&g_B[(size_t)d1 * H + lane * 4];

        float v0 = fmaxf(a0.x + bb0.x, 0.f) * w2.x
                 + fmaxf(a0.y + bb0.y, 0.f) * w2.y
                 + fmaxf(a0.z + bb0.z, 0.f) * w2.z
                 + fmaxf(a0.w + bb0.w, 0.f) * w2.w;
        float v1 = fmaxf(a1.x + bb1.x, 0.f) * w2.x
                 + fmaxf(a1.y + bb1.y, 0.f) * w2.y
                 + fmaxf(a1.z + bb1.z, 0.f) * w2.z
                 + fmaxf(a1.w + bb1.w, 0.f) * w2.w;

        #pragma unroll
        for (int off = 16; off > 0; off >>= 1) {
            v0 += __shfl_xor_sync(0xFFFFFFFFu, v0, off);
            v1 += __shfl_xor_sync(0xFFFFFFFFu, v1, off);
        }

        if (lane == 0) {
            out[e0] = v0 + b2v;
            if (has1) out[e1] = v1 + b2v;
        }
    }
}

// ---------------------------------------------------------------------------
extern "C" void kernel_launch(void* const* d_in, const int* in_sizes, int n_in,
                              void* d_out, int out_size)
{
    const float* user  = (const float*)d_in[0];
    const float* movie = (const float*)d_in[1];
    const int*   ei    = (const int*)d_in[2];
    const float* W1    = (const float*)d_in[3];
    const float* b1    = (const float*)d_in[4];
    const float* W2    = (const float*)d_in[5];
    const float* b2    = (const float*)d_in[6];
    float* out = (float*)d_out;

    int n_users  = in_sizes[0] / H;
    int n_movies = in_sizes[1] / H;
    int E        = in_sizes[2] / 2;
    if (n_users  > MAX_ROWS) n_users  = MAX_ROWS;
    if (n_movies > MAX_ROWS) n_movies = MAX_ROWS;

    float* dA = nullptr;
    float* dB = nullptr;
    cudaGetSymbolAddress((void**)&dA, g_A);
    cudaGetSymbolAddress((void**)&dB, g_B);

    const int smem_bytes = (H * H + TILE_ROWS * H) * (int)sizeof(float); // 96 KB
    static bool attr_set = false;
    if (!attr_set) {
        cudaFuncSetAttribute(precompute_kernel,
                             cudaFuncAttributeMaxDynamicSharedMemorySize,
                             smem_bytes);
        attr_set = true;
    }

    // A = user @ W1[:128] + b1
    {
        int blocks = (n_users + TILE_ROWS - 1) / TILE_ROWS;
        precompute_kernel<<<blocks, 256, smem_bytes>>>(user, W1, b1, dA, n_users);
    }
    // B = movie @ W1[128:]   (bias folded into A)
    {
        int blocks = (n_movies + TILE_ROWS - 1) / TILE_ROWS;
        precompute_kernel<<<blocks, 256, smem_bytes>>>(movie, W1 + H * H, nullptr, dB, n_movies);
    }
    // Edge scoring
    {
        int blocks = 148 * 8;  // 64 warps/SM at 256 thr/block
        edge_kernel<<<blocks, 256>>>(ei, W2, b2, out, E);
    }
}

// round 3
// speedup vs baseline: 1.3779x; 1.3779x over previous
#include <cuda_runtime.h>
#include <stdint.h>

#define H 128
#define MAX_ROWS 100000
#define BM 128          // rows per precompute block
#define PAD 4           // smem row padding (words)
#define LDW (H + PAD)   // 132

// Scratch tables: A = user @ W1_top + b1,  B = movie @ W1_bot
__device__ float g_A[(size_t)MAX_ROWS * H];
__device__ float g_B[(size_t)MAX_ROWS * H];

__device__ __forceinline__ uint32_t f2tf32(float f) {
    uint32_t r;
    asm("cvt.rna.tf32.f32 %0, %1;" : "=r"(r) : "f"(f));
    return r;
}

__device__ __forceinline__ void mma_tf32(float& c0, float& c1, float& c2, float& c3,
                                         uint32_t a0, uint32_t a1, uint32_t a2, uint32_t a3,
                                         uint32_t b0, uint32_t b1) {
    asm volatile(
        "mma.sync.aligned.m16n8k8.row.col.f32.tf32.tf32.f32 "
        "{%0,%1,%2,%3}, {%4,%5,%6,%7}, {%8,%9}, {%0,%1,%2,%3};"
        : "+f"(c0), "+f"(c1), "+f"(c2), "+f"(c3)
        : "r"(a0), "r"(a1), "r"(a2), "r"(a3), "r"(b0), "r"(b1));
}

// ---------------------------------------------------------------------------
// Precompute via tf32 tensor cores:
//   out[n_rows,128] = X[n_rows,128] @ W[128,128] (+ bias)
// 256 threads = 8 warps; warp w owns rows [w*16, w*16+16).
// Per warp: A frags (16 k-steps) resident in regs, 16 n-tiles x 16 k-steps mma.
// ---------------------------------------------------------------------------
__global__ __launch_bounds__(256, 1)
void precompute_mma(const float* __restrict__ X,
                    const float* __restrict__ W,
                    const float* __restrict__ bias,
                    float* __restrict__ out,
                    int n_rows)
{
    extern __shared__ uint32_t sm[];
    uint32_t* Xs = sm;                    // [BM][LDW]
    uint32_t* Ws = sm + BM * LDW;         // [H][LDW]

    const int tid  = threadIdx.x;
    const int row0 = blockIdx.x * BM;

    // Stage W (convert to tf32): 4096 float4 loads across 256 threads
    #pragma unroll
    for (int i = 0; i < 16; i++) {
        int idx = tid + i * 256;          // float4 index
        float4 v = ((const float4*)W)[idx];
        int r = idx >> 5;
        int c = (idx & 31) << 2;
        uint32_t* p = &Ws[r * LDW + c];
        p[0] = f2tf32(v.x); p[1] = f2tf32(v.y);
        p[2] = f2tf32(v.z); p[3] = f2tf32(v.w);
    }
    // Stage X tile (row-guarded, zero fill)
    #pragma unroll
    for (int i = 0; i < 16; i++) {
        int idx = tid + i * 256;
        int r = idx >> 5;
        int c4 = idx & 31;
        float4 v = make_float4(0.f, 0.f, 0.f, 0.f);
        if (row0 + r < n_rows)
            v = ((const float4*)X)[(size_t)(row0 + r) * 32 + c4];
        uint32_t* p = &Xs[r * LDW + (c4 << 2)];
        p[0] = f2tf32(v.x); p[1] = f2tf32(v.y);
        p[2] = f2tf32(v.z); p[3] = f2tf32(v.w);
    }
    __syncthreads();

    const int warp = tid >> 5;
    const int lane = tid & 31;
    const int wrow = warp << 4;           // warp's first row in tile
    const int ar   = lane >> 2;           // group id 0..7
    const int ac   = lane & 3;            // thread-in-group 0..3

    // Load all A fragments: 16 k-steps x 4 regs (conflict-free: 4*ar+ac distinct)
    uint32_t a[16][4];
    #pragma unroll
    for (int ks = 0; ks < 16; ks++) {
        int kb = ks << 3;
        a[ks][0] = Xs[(wrow + ar    ) * LDW + kb + ac    ];
        a[ks][1] = Xs[(wrow + ar + 8) * LDW + kb + ac    ];
        a[ks][2] = Xs[(wrow + ar    ) * LDW + kb + ac + 4];
        a[ks][3] = Xs[(wrow + ar + 8) * LDW + kb + ac + 4];
    }

    const int r_out0 = row0 + wrow + ar;
    const int r_out1 = r_out0 + 8;

    #pragma unroll
    for (int nt = 0; nt < 16; nt++) {
        const int n0 = nt << 3;
        float c0 = 0.f, c1 = 0.f, c2 = 0.f, c3 = 0.f;
        #pragma unroll
        for (int ks = 0; ks < 16; ks++) {
            int kb = ks << 3;
            uint32_t b0 = Ws[(kb + ac    ) * LDW + n0 + ar];
            uint32_t b1 = Ws[(kb + ac + 4) * LDW + n0 + ar];
            mma_tf32(c0, c1, c2, c3,
                     a[ks][0], a[ks][1], a[ks][2], a[ks][3], b0, b1);
        }
        float bx = 0.f, by = 0.f;
        if (bias) {
            bx = bias[n0 + 2 * ac];
            by = bias[n0 + 2 * ac + 1];
        }
        if (r_out0 < n_rows) {
            float2 st; st.x = c0 + bx; st.y = c1 + by;
            *(float2*)&out[(size_t)r_out0 * H + n0 + 2 * ac] = st;
        }
        if (r_out1 < n_rows) {
            float2 st; st.x = c2 + bx; st.y = c3 + by;
            *(float2*)&out[(size_t)r_out1 * H + n0 + 2 * ac] = st;
        }
    }
}

// ---------------------------------------------------------------------------
// Edge phase: out[e] = relu(A[src[e]] + B[dst[e]]) . W2 + b2
// One warp per edge, 2-edge unroll. L2-roofline-bound (~1.03 GB @ ~12.6 TB/s).
// ---------------------------------------------------------------------------
__global__ __launch_bounds__(256)
void edge_kernel(const int* __restrict__ ei,
                 const float* __restrict__ W2,
                 const float* __restrict__ b2,
                 float* __restrict__ out,
                 int E)
{
    const int lane = threadIdx.x & 31;
    const int gw   = (blockIdx.x * blockDim.x + threadIdx.x) >> 5;
    const int nw   = (gridDim.x * blockDim.x) >> 5;

    const float4 w2 = *(const float4*)&W2[lane * 4];
    const float  b2v = b2[0];

    for (int e0 = gw * 2; e0 < E; e0 += nw * 2) {
        const int e1    = e0 + 1;
        const bool has1 = (e1 < E);
        const int ee1   = has1 ? e1 : e0;

        int s0 = ei[e0],  d0 = ei[E + e0];
        int s1 = ei[ee1], d1 = ei[E + ee1];

        float4 a0  = *(const float4*)&g_A[(size_t)s0 * H + lane * 4];
        float4 bb0 = *(const float4*)&g_B[(size_t)d0 * H + lane * 4];
        float4 a1  = *(const float4*)&g_A[(size_t)s1 * H + lane * 4];
        float4 bb1 = *(const float4*)&g_B[(size_t)d1 * H + lane * 4];

        float v0 = fmaxf(a0.x + bb0.x, 0.f) * w2.x
                 + fmaxf(a0.y + bb0.y, 0.f) * w2.y
                 + fmaxf(a0.z + bb0.z, 0.f) * w2.z
                 + fmaxf(a0.w + bb0.w, 0.f) * w2.w;
        float v1 = fmaxf(a1.x + bb1.x, 0.f) * w2.x
                 + fmaxf(a1.y + bb1.y, 0.f) * w2.y
                 + fmaxf(a1.z + bb1.z, 0.f) * w2.z
                 + fmaxf(a1.w + bb1.w, 0.f) * w2.w;

        #pragma unroll
        for (int off = 16; off > 0; off >>= 1) {
            v0 += __shfl_xor_sync(0xFFFFFFFFu, v0, off);
            v1 += __shfl_xor_sync(0xFFFFFFFFu, v1, off);
        }

        if (lane == 0) {
            out[e0] = v0 + b2v;
            if (has1) out[e1] = v1 + b2v;
        }
    }
}

// ---------------------------------------------------------------------------
extern "C" void kernel_launch(void* const* d_in, const int* in_sizes, int n_in,
                              void* d_out, int out_size)
{
    const float* user  = (const float*)d_in[0];
    const float* movie = (const float*)d_in[1];
    const int*   ei    = (const int*)d_in[2];
    const float* W1    = (const float*)d_in[3];
    const float* b1    = (const float*)d_in[4];
    const float* W2    = (const float*)d_in[5];
    const float* b2    = (const float*)d_in[6];
    float* out = (float*)d_out;

    int n_users  = in_sizes[0] / H;
    int n_movies = in_sizes[1] / H;
    int E        = in_sizes[2] / 2;
    if (n_users  > MAX_ROWS) n_users  = MAX_ROWS;
    if (n_movies > MAX_ROWS) n_movies = MAX_ROWS;

    float* dA = nullptr;
    float* dB = nullptr;
    cudaGetSymbolAddress((void**)&dA, g_A);
    cudaGetSymbolAddress((void**)&dB, g_B);

    const int smem_bytes = (BM + H) * LDW * (int)sizeof(uint32_t);  // 132 KB
    static bool attr_set = false;
    if (!attr_set) {
        cudaFuncSetAttribute(precompute_mma,
                             cudaFuncAttributeMaxDynamicSharedMemorySize,
                             smem_bytes);
        attr_set = true;
    }

    // A = user @ W1[:128] + b1
    {
        int blocks = (n_users + BM - 1) / BM;
        precompute_mma<<<blocks, 256, smem_bytes>>>(user, W1, b1, dA, n_users);
    }
    // B = movie @ W1[128:]   (bias folded into A)
    {
        int blocks = (n_movies + BM - 1) / BM;
        precompute_mma<<<blocks, 256, smem_bytes>>>(movie, W1 + H * H, nullptr, dB, n_movies);
    }
    // Edge scoring
    {
        int blocks = 148 * 8;
        edge_kernel<<<blocks, 256>>>(ei, W2, b2, out, E);
    }
}

// round 4
// speedup vs baseline: 2.1659x; 1.5719x over previous
#include <cuda_runtime.h>
#include <cuda_fp16.h>
#include <stdint.h>

#define H 128
#define MAX_ROWS 100000
#define BM 128
#define LDH 136          // smem row pitch in halfs (272B): conflict-free ldmatrix

// Precomputed tables in fp16: A = user@W1_top + b1, B = movie@W1_bot
__device__ __half g_A[(size_t)MAX_ROWS * H];
__device__ __half g_B[(size_t)MAX_ROWS * H];

__device__ __forceinline__ uint32_t smem_u32(const void* p) {
    return (uint32_t)__cvta_generic_to_shared(p);
}

__device__ __forceinline__ void ldsm_x4(uint32_t& r0, uint32_t& r1,
                                        uint32_t& r2, uint32_t& r3, uint32_t addr) {
    asm volatile("ldmatrix.sync.aligned.m8n8.x4.shared.b16 {%0,%1,%2,%3}, [%4];"
                 : "=r"(r0), "=r"(r1), "=r"(r2), "=r"(r3) : "r"(addr));
}
__device__ __forceinline__ void ldsm_x4_t(uint32_t& r0, uint32_t& r1,
                                          uint32_t& r2, uint32_t& r3, uint32_t addr) {
    asm volatile("ldmatrix.sync.aligned.m8n8.x4.trans.shared.b16 {%0,%1,%2,%3}, [%4];"
                 : "=r"(r0), "=r"(r1), "=r"(r2), "=r"(r3) : "r"(addr));
}
__device__ __forceinline__ void mma16816(float& c0, float& c1, float& c2, float& c3,
                                         uint32_t a0, uint32_t a1, uint32_t a2, uint32_t a3,
                                         uint32_t b0, uint32_t b1) {
    asm volatile("mma.sync.aligned.m16n8k16.row.col.f32.f16.f16.f32 "
                 "{%0,%1,%2,%3}, {%4,%5,%6,%7}, {%8,%9}, {%0,%1,%2,%3};"
                 : "+f"(c0), "+f"(c1), "+f"(c2), "+f"(c3)
                 : "r"(a0), "r"(a1), "r"(a2), "r"(a3), "r"(b0), "r"(b1));
}

// ---------------------------------------------------------------------------
// Fused precompute (fp16 MMA): blocks [0, blocksA) -> A table,
// blocks [blocksA, ..) -> B table.  out[row,128] = X[row,:] @ W (+bias), fp16.
// 256 threads = 8 warps, warp w owns 16 rows. 68KB smem -> 2 CTAs/SM.
// ---------------------------------------------------------------------------
__global__ __launch_bounds__(256, 2)
void precompute_fp16(const float* __restrict__ user,
                     const float* __restrict__ movie,
                     const float* __restrict__ W1,
                     const float* __restrict__ b1,
                     int n_users, int n_movies, int blocksA)
{
    const bool isA = (int)blockIdx.x < blocksA;
    const float* X    = isA ? user : movie;
    const float* W    = isA ? W1   : (W1 + H * H);
    const float* bias = isA ? b1   : nullptr;
    __half* out       = isA ? g_A  : g_B;
    const int n_rows  = isA ? n_users : n_movies;
    const int bx      = isA ? (int)blockIdx.x : (int)blockIdx.x - blocksA;
    const int row0    = bx * BM;

    extern __shared__ __half sm[];
    __half* Xs = sm;               // [BM][LDH]
    __half* Ws = sm + BM * LDH;    // [H][LDH]

    const int tid = threadIdx.x;

    // Stage W: 4096 float4 across 256 threads, convert fp32 -> fp16
    #pragma unroll
    for (int i = 0; i < 16; i++) {
        int idx = tid + i * 256;
        float4 v = ((const float4*)W)[idx];
        int r = idx >> 5;
        int c = (idx & 31) << 2;
        __half2* p = (__half2*)&Ws[r * LDH + c];
        p[0] = __floats2half2_rn(v.x, v.y);
        p[1] = __floats2half2_rn(v.z, v.w);
    }
    // Stage X tile (row-guarded)
    #pragma unroll
    for (int i = 0; i < 16; i++) {
        int idx = tid + i * 256;
        int r = idx >> 5;
        int c4 = idx & 31;
        float4 v = make_float4(0.f, 0.f, 0.f, 0.f);
        if (row0 + r < n_rows)
            v = ((const float4*)X)[(size_t)(row0 + r) * 32 + c4];
        __half2* p = (__half2*)&Xs[r * LDH + (c4 << 2)];
        p[0] = __floats2half2_rn(v.x, v.y);
        p[1] = __floats2half2_rn(v.z, v.w);
    }
    __syncthreads();

    const int warp = tid >> 5;
    const int lane = tid & 31;
    const int wrow = warp << 4;
    const int g    = lane >> 2;    // 0..7
    const int t    = lane & 3;     // 0..3

    // ldmatrix base addresses (byte)
    const uint32_t xs_u = smem_u32(Xs);
    const uint32_t ws_u = smem_u32(Ws);
    // A: lane -> row (wrow + lane%16), half-col offset (lane/16)*8
    const uint32_t a_base = xs_u +
        (((wrow + (lane & 15)) * LDH + ((lane >> 4) << 3)) << 1);
    // B: lane -> k-row (lane%16), n-col offset (lane/16)*8 (covers 2 n-tiles)
    const uint32_t b_base = ws_u +
        ((((lane & 15)) * LDH + ((lane >> 4) << 3)) << 1);

    float acc[16][4];
    #pragma unroll
    for (int n = 0; n < 16; n++)
        acc[n][0] = acc[n][1] = acc[n][2] = acc[n][3] = 0.f;

    #pragma unroll
    for (int kb8 = 0; kb8 < 8; kb8++) {
        const int kb = kb8 << 4;   // k-block start (16 wide)
        uint32_t a0, a1, a2, a3;
        ldsm_x4(a0, a1, a2, a3, a_base + (kb << 1));

        uint32_t b[8][4];
        #pragma unroll
        for (int np = 0; np < 8; np++)
            ldsm_x4_t(b[np][0], b[np][1], b[np][2], b[np][3],
                      b_base + ((kb * LDH + (np << 4)) << 1));

        #pragma unroll
        for (int np = 0; np < 8; np++) {
            mma16816(acc[2*np][0], acc[2*np][1], acc[2*np][2], acc[2*np][3],
                     a0, a1, a2, a3, b[np][0], b[np][1]);
            mma16816(acc[2*np+1][0], acc[2*np+1][1], acc[2*np+1][2], acc[2*np+1][3],
                     a0, a1, a2, a3, b[np][2], b[np][3]);
        }
    }

    const int r_out0 = row0 + wrow + g;
    const int r_out1 = r_out0 + 8;

    #pragma unroll
    for (int nt = 0; nt < 16; nt++) {
        const int col = (nt << 3) + (t << 1);
        float bx = 0.f, by = 0.f;
        if (bias) { bx = bias[col]; by = bias[col + 1]; }
        if (r_out0 < n_rows)
            *(__half2*)&out[(size_t)r_out0 * H + col] =
                __floats2half2_rn(acc[nt][0] + bx, acc[nt][1] + by);
        if (r_out1 < n_rows)
            *(__half2*)&out[(size_t)r_out1 * H + col] =
                __floats2half2_rn(acc[nt][2] + bx, acc[nt][3] + by);
    }
}

// ---------------------------------------------------------------------------
// Edge phase: out[e] = relu(A[src[e]] + B[dst[e]]) . W2 + b2
// fp16 tables: 256B/row -> ~524B of L2 traffic per edge (tables L2-resident).
// One warp per edge, 2-edge unroll.
// ---------------------------------------------------------------------------
__global__ __launch_bounds__(256)
void edge_kernel(const int* __restrict__ ei,
                 const float* __restrict__ W2,
                 const float* __restrict__ b2,
                 float* __restrict__ out,
                 int E)
{
    const int lane = threadIdx.x & 31;
    const int gw   = (blockIdx.x * blockDim.x + threadIdx.x) >> 5;
    const int nw   = (gridDim.x * blockDim.x) >> 5;

    const float4 w2 = *(const float4*)&W2[lane * 4];   // cols 4l..4l+3
    const float  b2v = b2[0];
    const __half2 hz = __floats2half2_rn(0.f, 0.f);

    for (int e0 = gw * 2; e0 < E; e0 += nw * 2) {
        const int e1    = e0 + 1;
        const bool has1 = (e1 < E);
        const int ee1   = has1 ? e1 : e0;

        int s0 = ei[e0],  d0 = ei[E + e0];
        int s1 = ei[ee1], d1 = ei[E + ee1];

        // 4 halfs (8B) per lane per row
        uint2 ua0 = *(const uint2*)&g_A[(size_t)s0 * H + lane * 4];
        uint2 ub0 = *(const uint2*)&g_B[(size_t)d0 * H + lane * 4];
        uint2 ua1 = *(const uint2*)&g_A[(size_t)s1 * H + lane * 4];
        uint2 ub1 = *(const uint2*)&g_B[(size_t)d1 * H + lane * 4];

        __half2 h0a = __hmax2(__hadd2(*(__half2*)&ua0.x, *(__half2*)&ub0.x), hz);
        __half2 h0b = __hmax2(__hadd2(*(__half2*)&ua0.y, *(__half2*)&ub0.y), hz);
        __half2 h1a = __hmax2(__hadd2(*(__half2*)&ua1.x, *(__half2*)&ub1.x), hz);
        __half2 h1b = __hmax2(__hadd2(*(__half2*)&ua1.y, *(__half2*)&ub1.y), hz);

        float2 f0a = __half22float2(h0a);
        float2 f0b = __half22float2(h0b);
        float2 f1a = __half22float2(h1a);
        float2 f1b = __half22float2(h1b);

        float v0 = f0a.x * w2.x + f0a.y * w2.y + f0b.x * w2.z + f0b.y * w2.w;
        float v1 = f1a.x * w2.x + f1a.y * w2.y + f1b.x * w2.z + f1b.y * w2.w;

        #pragma unroll
        for (int off = 16; off > 0; off >>= 1) {
            v0 += __shfl_xor_sync(0xFFFFFFFFu, v0, off);
            v1 += __shfl_xor_sync(0xFFFFFFFFu, v1, off);
        }

        if (lane == 0) {
            out[e0] = v0 + b2v;
            if (has1) out[e1] = v1 + b2v;
        }
    }
}

// ---------------------------------------------------------------------------
extern "C" void kernel_launch(void* const* d_in, const int* in_sizes, int n_in,
                              void* d_out, int out_size)
{
    const float* user  = (const float*)d_in[0];
    const float* movie = (const float*)d_in[1];
    const int*   ei    = (const int*)d_in[2];
    const float* W1    = (const float*)d_in[3];
    const float* b1    = (const float*)d_in[4];
    const float* W2    = (const float*)d_in[5];
    const float* b2    = (const float*)d_in[6];
    float* out = (float*)d_out;

    int n_users  = in_sizes[0] / H;
    int n_movies = in_sizes[1] / H;
    int E        = in_sizes[2] / 2;
    if (n_users  > MAX_ROWS) n_users  = MAX_ROWS;
    if (n_movies > MAX_ROWS) n_movies = MAX_ROWS;

    const int blocksA = (n_users  + BM - 1) / BM;
    const int blocksB = (n_movies + BM - 1) / BM;

    const int smem_bytes = (BM + H) * LDH * (int)sizeof(__half);  // 68 KB
    static bool attr_set = false;
    if (!attr_set) {
        cudaFuncSetAttribute(precompute_fp16,
                             cudaFuncAttributeMaxDynamicSharedMemorySize,
                             smem_bytes);
        attr_set = true;
    }

    precompute_fp16<<<blocksA + blocksB, 256, smem_bytes>>>(
        user, movie, W1, b1, n_users, n_movies, blocksA);

    edge_kernel<<<148 * 8, 256>>>(ei, W2, b2, out, E);
}

// round 5
// speedup vs baseline: 2.6754x; 1.2352x over previous
#include <cuda_runtime.h>
#include <cuda_fp16.h>
#include <stdint.h>

#define H 128
#define MAX_ROWS 100000
#define BM 128
#define LDH 136          // W smem row pitch in halfs (272B): conflict-free ldmatrix

// Precomputed tables in fp16: A = user@W1_top + b1, B = movie@W1_bot
__device__ __half g_A[(size_t)MAX_ROWS * H];
__device__ __half g_B[(size_t)MAX_ROWS * H];

__device__ __forceinline__ uint32_t smem_u32(const void* p) {
    return (uint32_t)__cvta_generic_to_shared(p);
}
__device__ __forceinline__ void ldsm_x4_t(uint32_t& r0, uint32_t& r1,
                                          uint32_t& r2, uint32_t& r3, uint32_t addr) {
    asm volatile("ldmatrix.sync.aligned.m8n8.x4.trans.shared.b16 {%0,%1,%2,%3}, [%4];"
                 : "=r"(r0), "=r"(r1), "=r"(r2), "=r"(r3) : "r"(addr));
}
__device__ __forceinline__ void mma16816(float& c0, float& c1, float& c2, float& c3,
                                         uint32_t a0, uint32_t a1, uint32_t a2, uint32_t a3,
                                         uint32_t b0, uint32_t b1) {
    asm volatile("mma.sync.aligned.m16n8k16.row.col.f32.f16.f16.f32 "
                 "{%0,%1,%2,%3}, {%4,%5,%6,%7}, {%8,%9}, {%0,%1,%2,%3};"
                 : "+f"(c0), "+f"(c1), "+f"(c2), "+f"(c3)
                 : "r"(a0), "r"(a1), "r"(a2), "r"(a3), "r"(b0), "r"(b1));
}
__device__ __forceinline__ uint32_t pack_h2(float x, float y) {
    __half2 h = __floats2half2_rn(x, y);
    return *(uint32_t*)&h;
}

// ---------------------------------------------------------------------------
// Fused precompute (fp16 MMA): blocks [0, blocksA) -> A table, rest -> B.
// A-fragments loaded DIRECTLY from gmem (no X smem staging); W staged in smem.
// 256 threads = 8 warps; warp w owns 16 rows. 34KB smem.
// ---------------------------------------------------------------------------
__global__ __launch_bounds__(256, 2)
void precompute_fp16(const float* __restrict__ user,
                     const float* __restrict__ movie,
                     const float* __restrict__ W1,
                     const float* __restrict__ b1,
                     int n_users, int n_movies, int blocksA)
{
    const bool isA = (int)blockIdx.x < blocksA;
    const float* X    = isA ? user : movie;
    const float* W    = isA ? W1   : (W1 + H * H);
    const float* bias = isA ? b1   : nullptr;
    __half* out       = isA ? g_A  : g_B;
    const int n_rows  = isA ? n_users : n_movies;
    const int bx      = isA ? (int)blockIdx.x : (int)blockIdx.x - blocksA;
    const int row0    = bx * BM;

    extern __shared__ __half sm[];
    __half* Ws = sm;               // [H][LDH]

    const int tid = threadIdx.x;

    // Stage W: 4096 float4 across 256 threads, fp32 -> fp16
    #pragma unroll
    for (int i = 0; i < 16; i++) {
        int idx = tid + i * 256;
        float4 v = ((const float4*)W)[idx];
        int r = idx >> 5;
        int c = (idx & 31) << 2;
        uint32_t* p = (uint32_t*)&Ws[r * LDH + c];
        p[0] = pack_h2(v.x, v.y);
        p[1] = pack_h2(v.z, v.w);
    }

    const int warp = tid >> 5;
    const int lane = tid & 31;
    const int wrow = warp << 4;
    const int g    = lane >> 2;    // 0..7
    const int t    = lane & 3;     // 0..3

    const int r0 = row0 + wrow + g;
    const int r1 = r0 + 8;
    const bool ok0 = r0 < n_rows;
    const bool ok1 = r1 < n_rows;

    // Direct gmem A-fragment loads (mma m16n8k16 layout), all issued up front.
    const float* p0 = X + (size_t)r0 * H + 2 * t;
    const float* p1 = X + (size_t)r1 * H + 2 * t;
    uint32_t afr[8][4];
    #pragma unroll
    for (int kb8 = 0; kb8 < 8; kb8++) {
        const int kb = kb8 << 4;
        float2 x0 = ok0 ? *(const float2*)(p0 + kb)     : make_float2(0.f, 0.f);
        float2 x1 = ok1 ? *(const float2*)(p1 + kb)     : make_float2(0.f, 0.f);
        float2 x2 = ok0 ? *(const float2*)(p0 + kb + 8) : make_float2(0.f, 0.f);
        float2 x3 = ok1 ? *(const float2*)(p1 + kb + 8) : make_float2(0.f, 0.f);
        afr[kb8][0] = pack_h2(x0.x, x0.y);
        afr[kb8][1] = pack_h2(x1.x, x1.y);
        afr[kb8][2] = pack_h2(x2.x, x2.y);
        afr[kb8][3] = pack_h2(x3.x, x3.y);
    }
    __syncthreads();

    // B ldmatrix base: lane -> k-row (lane%16), n-col offset (lane/16)*8
    const uint32_t b_base = smem_u32(Ws) +
        ((((lane & 15)) * LDH + ((lane >> 4) << 3)) << 1);

    float acc[16][4];
    #pragma unroll
    for (int n = 0; n < 16; n++)
        acc[n][0] = acc[n][1] = acc[n][2] = acc[n][3] = 0.f;

    #pragma unroll
    for (int kb8 = 0; kb8 < 8; kb8++) {
        const int kb = kb8 << 4;
        uint32_t b[8][4];
        #pragma unroll
        for (int np = 0; np < 8; np++)
            ldsm_x4_t(b[np][0], b[np][1], b[np][2], b[np][3],
                      b_base + ((kb * LDH + (np << 4)) << 1));
        #pragma unroll
        for (int np = 0; np < 8; np++) {
            mma16816(acc[2*np][0], acc[2*np][1], acc[2*np][2], acc[2*np][3],
                     afr[kb8][0], afr[kb8][1], afr[kb8][2], afr[kb8][3],
                     b[np][0], b[np][1]);
            mma16816(acc[2*np+1][0], acc[2*np+1][1], acc[2*np+1][2], acc[2*np+1][3],
                     afr[kb8][0], afr[kb8][1], afr[kb8][2], afr[kb8][3],
                     b[np][2], b[np][3]);
        }
    }

    #pragma unroll
    for (int nt = 0; nt < 16; nt++) {
        const int col = (nt << 3) + (t << 1);
        float bx = 0.f, by = 0.f;
        if (bias) { bx = bias[col]; by = bias[col + 1]; }
        if (ok0)
            *(__half2*)&out[(size_t)r0 * H + col] =
                __floats2half2_rn(acc[nt][0] + bx, acc[nt][1] + by);
        if (ok1)
            *(__half2*)&out[(size_t)r1 * H + col] =
                __floats2half2_rn(acc[nt][2] + bx, acc[nt][3] + by);
    }
}

// ---------------------------------------------------------------------------
// Edge phase: out[e] = relu(A[src[e]] + B[dst[e]]) . W2 + b2
// 16 lanes per edge (16B/lane), 4 edges per warp-iteration.
// Pair packing makes the reduction 4 butterfly levels with no merge step.
// ---------------------------------------------------------------------------
__device__ __forceinline__ float dot8(uint4 ua, uint4 ub,
                                      __half2 w0, __half2 w1,
                                      __half2 w2, __half2 w3, __half2 hz) {
    __half2 h0 = __hmax2(__hadd2(*(__half2*)&ua.x, *(__half2*)&ub.x), hz);
    __half2 h1 = __hmax2(__hadd2(*(__half2*)&ua.y, *(__half2*)&ub.y), hz);
    __half2 h2 = __hmax2(__hadd2(*(__half2*)&ua.z, *(__half2*)&ub.z), hz);
    __half2 h3 = __hmax2(__hadd2(*(__half2*)&ua.w, *(__half2*)&ub.w), hz);
    __half2 c1 = __hfma2(h1, w1, __hmul2(h0, w0));
    __half2 c2 = __hfma2(h3, w3, __hmul2(h2, w2));
    float2 f1 = __half22float2(c1);
    float2 f2 = __half22float2(c2);
    return (f1.x + f1.y) + (f2.x + f2.y);
}

__global__ __launch_bounds__(256)
void edge_kernel(const int* __restrict__ ei,
                 const float* __restrict__ W2,
                 const float* __restrict__ b2,
                 float* __restrict__ out,
                 int E)
{
    const int lane = threadIdx.x & 31;
    const int half = lane >> 4;        // which edge of the pair
    const int q    = lane & 15;        // 16B chunk within the row
    const int gw   = (blockIdx.x * blockDim.x + threadIdx.x) >> 5;
    const int nw   = (gridDim.x * blockDim.x) >> 5;

    // W2 slice for this lane: cols q*8 .. q*8+7 as 4 half2
    float4 wlo = *(const float4*)&W2[q * 8];
    float4 whi = *(const float4*)&W2[q * 8 + 4];
    const __half2 w0 = __floats2half2_rn(wlo.x, wlo.y);
    const __half2 w1 = __floats2half2_rn(wlo.z, wlo.w);
    const __half2 w2 = __floats2half2_rn(whi.x, whi.y);
    const __half2 w3 = __floats2half2_rn(whi.z, whi.w);
    const float b2v = b2[0];
    const __half2 hz = __float2half2_rn(0.f);

    if ((E & 3) == 0) {
        for (int e0 = gw * 4; e0 < E; e0 += nw * 4) {
            int4 sq = *(const int4*)&ei[e0];
            int4 dq = *(const int4*)&ei[E + e0];
            int sA = half ? sq.y : sq.x;
            int dA = half ? dq.y : dq.x;
            int sB = half ? sq.w : sq.z;
            int dB = half ? dq.w : dq.z;

            uint4 a0  = *(const uint4*)&g_A[((size_t)sA << 7) + (q << 3)];
            uint4 bb0 = *(const uint4*)&g_B[((size_t)dA << 7) + (q << 3)];
            uint4 a1  = *(const uint4*)&g_A[((size_t)sB << 7) + (q << 3)];
            uint4 bb1 = *(const uint4*)&g_B[((size_t)dB << 7) + (q << 3)];

            float v0 = dot8(a0, bb0, w0, w1, w2, w3, hz);  // edge e0|e1 by half
            float v1 = dot8(a1, bb1, w0, w1, w2, w3, hz);  // edge e2|e3 by half

            #pragma unroll
            for (int off = 8; off > 0; off >>= 1) {
                v0 += __shfl_xor_sync(0xFFFFFFFFu, v0, off);
                v1 += __shfl_xor_sync(0xFFFFFFFFu, v1, off);
            }
            if (q == 0) {
                out[e0 + half]     = v0 + b2v;
                out[e0 + 2 + half] = v1 + b2v;
            }
        }
    } else {
        // Generic fallback (E not multiple of 4): one edge per warp.
        for (int e = gw; e < E; e += nw) {
            int s = ei[e], d = ei[E + e];
            uint2 ua = *(const uint2*)&g_A[(size_t)s * H + lane * 4];
            uint2 ub = *(const uint2*)&g_B[(size_t)d * H + lane * 4];
            __half2 h0 = __hmax2(__hadd2(*(__half2*)&ua.x, *(__half2*)&ub.x), hz);
            __half2 h1 = __hmax2(__hadd2(*(__half2*)&ua.y, *(__half2*)&ub.y), hz);
            float2 f0 = __half22float2(h0);
            float2 f1 = __half22float2(h1);
            float4 wv = *(const float4*)&W2[lane * 4];
            float v = f0.x * wv.x + f0.y * wv.y + f1.x * wv.z + f1.y * wv.w;
            #pragma unroll
            for (int off = 16; off > 0; off >>= 1)
                v += __shfl_xor_sync(0xFFFFFFFFu, v, off);
            if (lane == 0) out[e] = v + b2v;
        }
    }
}

// ---------------------------------------------------------------------------
extern "C" void kernel_launch(void* const* d_in, const int* in_sizes, int n_in,
                              void* d_out, int out_size)
{
    const float* user  = (const float*)d_in[0];
    const float* movie = (const float*)d_in[1];
    const int*   ei    = (const int*)d_in[2];
    const float* W1    = (const float*)d_in[3];
    const float* b1    = (const float*)d_in[4];
    const float* W2    = (const float*)d_in[5];
    const float* b2    = (const float*)d_in[6];
    float* out = (float*)d_out;

    int n_users  = in_sizes[0] / H;
    int n_movies = in_sizes[1] / H;
    int E        = in_sizes[2] / 2;
    if (n_users  > MAX_ROWS) n_users  = MAX_ROWS;
    if (n_movies > MAX_ROWS) n_movies = MAX_ROWS;

    const int blocksA = (n_users  + BM - 1) / BM;
    const int blocksB = (n_movies + BM - 1) / BM;

    const int smem_bytes = H * LDH * (int)sizeof(__half);  // 34816 B < 48KB default

    precompute_fp16<<<blocksA + blocksB, 256, smem_bytes>>>(
        user, movie, W1, b1, n_users, n_movies, blocksA);

    edge_kernel<<<148 * 8, 256>>>(ei, W2, b2, out, E);
}